// round 14
// baseline (speedup 1.0000x reference)
#include <cuda_runtime.h>

#define NVEH 4096
#define NT 256
#define PAST 25
#define LEADLEN (NT + PAST - 1)   // 280
#define NQUAD (NVEH / 4)          // 1024
#define WARPS_PER_CTA 7
#define NCTA ((NQUAD + WARPS_PER_CTA - 1) / WARPS_PER_CTA)   // 147
#define NTHREADS (WARPS_PER_CTA * 32)                         // 224

typedef unsigned long long ull;

// ---- shared memory layout (float offsets) ----
#define W1_OFF    0        // 288  : conv1_w [3][3][32]
#define B1_OFF    288      // 32
#define B2P_OFF   320      // 64   : float2 {b2[c], b2[c+32]}
#define W2X_OFF   384      // 4096 : float4 [ci*32+c] = {w0[c], w0[c+32], w1[c], w1[c+32]}
#define W2K2_OFF  4480     // 2048 : float4 [cp*32+c] = {k2[2cp][c], k2[2cp][c+32], k2[2cp+1][c], k2[2cp+1][c+32]}
#define WD2X_OFF  6528     // 3840 : ull2 [(q*6+jj)*32+c] = {pair_i, pair_{i+32}}
#define BD2_OFF   10368    // 10
#define WD1_OFF   10378    // 10
#define BD1_OFF   10388    // 1 (+3 pad)
#define XR_OFF    10392    // window ring: 14 sets * 32 slots * 8 floats = 3584
#define PQ_OFF    (XR_OFF + 14 * 32 * 8)            // 13976 : pool1 circular, 14*2*13*32 float2
#define SC_OFF    (PQ_OFF + 14 * 2 * 13 * 32 * 2)   // 37272 : conv2 odd state, 14*2*11*32 ull
#define SMEM_FLOATS (SC_OFF + 14 * 2 * 11 * 32 * 2) // 56984 floats = 227936 B

__device__ __forceinline__ ull ffma2(ull a, ull b, ull c) {
    ull d;
    asm("fma.rn.f32x2 %0, %1, %2, %3;" : "=l"(d) : "l"(a), "l"(b), "l"(c));
    return d;
}
__device__ __forceinline__ ull addf32x2(ull a, ull b) {
    ull d;
    asm("add.rn.f32x2 %0, %1, %2;" : "=l"(d) : "l"(a), "l"(b));
    return d;
}
__device__ __forceinline__ void unpk(ull v, float& lo, float& hi) {
    asm("mov.b64 {%0, %1}, %2;" : "=f"(lo), "=f"(hi) : "l"(v));
}
__device__ __forceinline__ ull pkdup(float x) {
    ull d;
    asm("mov.b64 %0, {%1, %1};" : "=l"(d) : "f"(x));
    return d;
}
__device__ __forceinline__ int wrap13(int x) { return x >= 13 ? x - 13 : x; }
__device__ __forceinline__ int wrap11(int x) { return x >= 11 ? x - 11 : x; }

__global__ void __launch_bounds__(NTHREADS, 1)
rnncf_kernel(const float* __restrict__ lead, const float* __restrict__ cur,
             const float* __restrict__ w1g, const float* __restrict__ b1g,
             const float* __restrict__ w2g, const float* __restrict__ b2g,
             const float* __restrict__ wd2g, const float* __restrict__ bd2g,
             const float* __restrict__ wd1g, const float* __restrict__ bd1g,
             float* __restrict__ out)
{
    extern __shared__ float sm[];
    const int tid = threadIdx.x;

    // ---------- cooperative weight staging ----------
    for (int i = tid; i < 288; i += NTHREADS) sm[W1_OFF + i] = w1g[i];
    for (int i = tid; i < 32;  i += NTHREADS) sm[B1_OFF + i] = b1g[i];
    {
        float2* b2p_s = (float2*)(sm + B2P_OFF);
        for (int i = tid; i < 32; i += NTHREADS)
            b2p_s[i] = make_float2(b2g[i], b2g[i + 32]);
        float4* w2x_s = (float4*)(sm + W2X_OFF);
        for (int i = tid; i < 1024; i += NTHREADS) {
            int ci = i >> 5, c = i & 31;
            w2x_s[i] = make_float4(w2g[ci * 64 + c],        w2g[ci * 64 + c + 32],
                                   w2g[(32 + ci) * 64 + c], w2g[(32 + ci) * 64 + c + 32]);
        }
        float4* w2k2_s = (float4*)(sm + W2K2_OFF);
        for (int i = tid; i < 512; i += NTHREADS) {
            int cp = i >> 5, c = i & 31;
            w2k2_s[i] = make_float4(w2g[(64 + 2 * cp) * 64 + c],     w2g[(64 + 2 * cp) * 64 + c + 32],
                                    w2g[(64 + 2 * cp + 1) * 64 + c], w2g[(64 + 2 * cp + 1) * 64 + c + 32]);
        }
        float4* wdx_s = (float4*)(sm + WD2X_OFF);
        for (int i = tid; i < 960; i += NTHREADS) {
            int q = i / 192, r = i - q * 192;
            int jj = r >> 5, c = r & 31;
            int ii = jj * 64 + c;
            wdx_s[i] = make_float4(wd2g[ii * 10 + 2 * q],        wd2g[ii * 10 + 2 * q + 1],
                                   wd2g[(ii + 32) * 10 + 2 * q], wd2g[(ii + 32) * 10 + 2 * q + 1]);
        }
    }
    for (int i = tid; i < 10; i += NTHREADS) sm[BD2_OFF + i] = bd2g[i];
    for (int i = tid; i < 10; i += NTHREADS) sm[WD1_OFF + i] = wd1g[i];
    if (tid == 0) sm[BD1_OFF] = bd1g[0];
    __syncthreads();

    const int wid = tid >> 5, lane = tid & 31;
    const int quad = blockIdx.x * WARPS_PER_CTA + wid;
    if (quad >= NQUAD) return;

    // window rings (32 slots * 8 floats per set)
    float* xr0 = sm + XR_OFF + (wid * 2 + 0) * 256;
    float* xr1 = sm + XR_OFF + (wid * 2 + 1) * 256;
    // pool1 circular buffers: [set][parity]
    float2* pqE0 = (float2*)(sm + PQ_OFF) + ((wid * 2 + 0) * 2 + 0) * (13 * 32);
    float2* pqO0 = (float2*)(sm + PQ_OFF) + ((wid * 2 + 0) * 2 + 1) * (13 * 32);
    float2* pqE1 = (float2*)(sm + PQ_OFF) + ((wid * 2 + 1) * 2 + 0) * (13 * 32);
    float2* pqO1 = (float2*)(sm + PQ_OFF) + ((wid * 2 + 1) * 2 + 1) * (13 * 32);
    const ulonglong2* qE0 = (const ulonglong2*)pqE0;
    const ulonglong2* qO0 = (const ulonglong2*)pqO0;
    const ulonglong2* qE1 = (const ulonglong2*)pqE1;
    const ulonglong2* qO1 = (const ulonglong2*)pqO1;
    // conv2 odd-parity circular state (11 slots)
    ull* ScLo0 = (ull*)(sm + SC_OFF) + (wid * 2 + 0) * (2 * 11 * 32);
    ull* ScHi0 = ScLo0 + 11 * 32;
    ull* ScLo1 = (ull*)(sm + SC_OFF) + (wid * 2 + 1) * (2 * 11 * 32);
    ull* ScHi1 = ScLo1 + 11 * 32;
    const float4* w2xf   = (const float4*)(sm + W2X_OFF);
    const float4* w2k2f4 = (const float4*)(sm + W2K2_OFF);
    const ulonglong2* wdx = (const ulonglong2*)(sm + WD2X_OFF);

    const float2* lead2base = (const float2*)lead + (size_t)(4 * quad) * LEADLEN;
    float2*       out2base  = (float2*)out + (size_t)(4 * quad) * NT;

    // hoisted packed constants
    ull w1d[9];
    #pragma unroll
    for (int i = 0; i < 9; ++i) w1d[i] = pkdup(sm[W1_OFF + i * 32 + lane]);
    const ull b1d = pkdup(sm[B1_OFF + lane]);
    ull b2lo, b2hi;
    {
        float2 b2v = ((const float2*)(sm + B2P_OFF))[lane];
        b2lo = pkdup(b2v.x);
        b2hi = pkdup(b2v.y);
    }

    // ---------- window init: one-time full publish into the rings ----------
    float p24v[4], s24v[4];
    {
        float2 xw0[2], xw1[2], xw2[2];
        #pragma unroll
        for (int s = 0; s < 2; ++s) {
            xw0[s] = make_float2(0.f, 0.f);
            xw1[s] = make_float2(0.f, 0.f);
            xw2[s] = make_float2(0.f, 0.f);
        }
        float tp[4] = {0.f, 0.f, 0.f, 0.f}, ts[4] = {0.f, 0.f, 0.f, 0.f};
        if (lane < PAST) {
            const float2* cur2base = (const float2*)cur + (size_t)(4 * quad) * PAST;
            #pragma unroll
            for (int i = 0; i < 4; ++i) {
                float2 cs = cur2base[i * PAST + lane];
                float2 ld = lead2base[i * LEADLEN + lane];
                float X0 = (ld.x - cs.x) * (1.0f / 200.0f);
                float X1 = cs.y * (1.0f / 40.0f);
                float X2 = ld.y * (1.0f / 40.0f);
                int s = i >> 1;
                if ((i & 1) == 0) { xw0[s].x = X0; xw1[s].x = X1; xw2[s].x = X2; }
                else              { xw0[s].y = X0; xw1[s].y = X1; xw2[s].y = X2; }
                tp[i] = cs.x; ts[i] = cs.y;
            }
            // step-0 base is 0: column lane -> slot lane
            *(float4*)(xr0 + lane * 8)     = make_float4(xw0[0].x, xw0[0].y, xw1[0].x, xw1[0].y);
            *(float2*)(xr0 + lane * 8 + 4) = xw2[0];
            *(float4*)(xr1 + lane * 8)     = make_float4(xw0[1].x, xw0[1].y, xw1[1].x, xw1[1].y);
            *(float2*)(xr1 + lane * 8 + 4) = xw2[1];
        }
        #pragma unroll
        for (int i = 0; i < 4; ++i) {
            p24v[i] = __shfl_sync(0xffffffffu, tp[i], 24);
            s24v[i] = __shfl_sync(0xffffffffu, ts[i], 24);
        }
        __syncwarp();
    }
    float2 ldnv[4];

    // circular bases
    int bPe = 0, bPo = 0, bS = 0;
    int so7[7];      // pool1 read offsets (ulonglong2 units) for conv2_inc

    // ---------- helpers ----------
    auto rcol = [&](const float* xr, int bX, int r, ulonglong2& u, ull& v) {
        int o = ((bX + r) & 31) * 8;
        u = *(const ulonglong2*)(xr + o);
        v = *(const ull*)(xr + o + 4);
    };
    auto c1p3 = [&](ulonglong2 a01, ull a2, ulonglong2 b01, ull b2_, ulonglong2 c01, ull c2) -> ull {
        ull h = b1d;
        h = ffma2(a01.x, w1d[0], h); h = ffma2(a01.y, w1d[1], h); h = ffma2(a2,  w1d[2], h);
        h = ffma2(b01.x, w1d[3], h); h = ffma2(b01.y, w1d[4], h); h = ffma2(b2_, w1d[5], h);
        h = ffma2(c01.x, w1d[6], h); h = ffma2(c01.y, w1d[7], h); h = ffma2(c2,  w1d[8], h);
        return h;
    };
    auto poolpair = [&](ull h0, ull h1) -> float2 {
        float f0A, f0B, f1A, f1B;
        unpk(h0, f0A, f0B); unpk(h1, f1A, f1B);
        return make_float2(fmaxf(fmaxf(f0A, 0.f), fmaxf(f1A, 0.f)),
                           fmaxf(fmaxf(f0B, 0.f), fmaxf(f1B, 0.f)));
    };
    auto poolone = [&](ull h0) -> float2 {
        float f0A, f0B;
        unpk(h0, f0A, f0B);
        return make_float2(fmaxf(f0A, 0.f), fmaxf(f0B, 0.f));
    };

    // seeds: all 13 pool1 slots from the ring (edge positions avoid pad loads)
    auto conv1_full_ring = [&](const float* xr, float2* pd, int bX) {
        ulonglong2 b01, c01; ull b2_, c2;
        rcol(xr, bX, 0, b01, b2_);   // col0
        rcol(xr, bX, 1, c01, c2);    // col1
        ull h0 = b1d;                // pos0 = pad, c0, c1
        h0 = ffma2(b01.x, w1d[3], h0); h0 = ffma2(b01.y, w1d[4], h0); h0 = ffma2(b2_, w1d[5], h0);
        h0 = ffma2(c01.x, w1d[6], h0); h0 = ffma2(c01.y, w1d[7], h0); h0 = ffma2(c2,  w1d[8], h0);
        ulonglong2 d01; ull d2;
        rcol(xr, bX, 2, d01, d2);    // col2
        ull h1 = c1p3(b01, b2_, c01, c2, d01, d2);   // pos1
        pd[0 * 32 + lane] = poolpair(h0, h1);
        // rolling: b=col(2m-1), c=col(2m) entering iteration m
        b01 = c01; b2_ = c2; c01 = d01; c2 = d2;     // b=col1, c=col2
        #pragma unroll
        for (int m = 1; m < 12; ++m) {
            ulonglong2 C01, D01; ull C2, D2;
            rcol(xr, bX, 2 * m + 1, C01, C2);
            rcol(xr, bX, 2 * m + 2, D01, D2);
            ull g0 = c1p3(b01, b2_, c01, c2, C01, C2);   // pos 2m
            ull g1 = c1p3(c01, c2, C01, C2, D01, D2);    // pos 2m+1
            pd[m * 32 + lane] = poolpair(g0, g1);
            b01 = C01; b2_ = C2; c01 = D01; c2 = D2;
        }
        // slot 12: pos24 = c23, c24, pad  (b=col23, c=col24 after loop)
        ull g = b1d;
        g = ffma2(b01.x, w1d[0], g); g = ffma2(b01.y, w1d[1], g); g = ffma2(b2_, w1d[2], g);
        g = ffma2(c01.x, w1d[3], g); g = ffma2(c01.y, w1d[4], g); g = ffma2(c2,  w1d[5], g);
        pd[12 * 32 + lane] = poolone(g);
    };

    // steady-state: fresh conv positions {0,1,22,23,24} only
    auto conv1_fresh_ring = [&](const float* xr, float2* pd, int bX,
                                int w0i, int w11i, int w12i) {
        ulonglong2 u0, u1, u2; ull v0, v1, v2;
        rcol(xr, bX, 0, u0, v0);
        rcol(xr, bX, 1, u1, v1);
        rcol(xr, bX, 2, u2, v2);
        ull h0 = b1d;   // pos0 = pad, c0, c1
        h0 = ffma2(u0.x, w1d[3], h0); h0 = ffma2(u0.y, w1d[4], h0); h0 = ffma2(v0, w1d[5], h0);
        h0 = ffma2(u1.x, w1d[6], h0); h0 = ffma2(u1.y, w1d[7], h0); h0 = ffma2(v1, w1d[8], h0);
        ull h1 = c1p3(u0, v0, u1, v1, u2, v2);   // pos1
        pd[w0i * 32 + lane] = poolpair(h0, h1);

        ulonglong2 a, b, c, d; ull av, bv, cv, dv;
        rcol(xr, bX, 21, a, av);
        rcol(xr, bX, 22, b, bv);
        rcol(xr, bX, 23, c, cv);
        rcol(xr, bX, 24, d, dv);
        ull g0 = c1p3(a, av, b, bv, c, cv);   // pos22
        ull g1 = c1p3(b, bv, c, cv, d, dv);   // pos23
        ull g2 = b1d;                          // pos24 = c23, c24, pad
        g2 = ffma2(c.x, w1d[0], g2); g2 = ffma2(c.y, w1d[1], g2); g2 = ffma2(cv, w1d[2], g2);
        g2 = ffma2(d.x, w1d[3], g2); g2 = ffma2(d.y, w1d[4], g2); g2 = ffma2(dv, w1d[5], g2);
        pd[w11i * 32 + lane] = poolpair(g0, g1);
        pd[w12i * 32 + lane] = poolone(g2);
    };

    // seeds: all 11 conv2 positions for one set (buffer at base 0)
    auto conv2_full = [&](const ulonglong2* q, ull* Lo, ull* Hi) {
        #pragma unroll
        for (int j = 0; j < 11; ++j) { Lo[j] = b2lo; Hi[j] = b2hi; }
        #pragma unroll 1
        for (int cp = 0; cp < 16; ++cp) {
            float4 wa0 = w2xf[(2 * cp)     * 32 + lane];
            float4 wa1 = w2xf[(2 * cp + 1) * 32 + lane];
            float4 kk  = w2k2f4[cp * 32 + lane];
            ull d00 = pkdup(wa0.x), d01 = pkdup(wa0.y), d10 = pkdup(wa0.z), d11 = pkdup(wa0.w);
            ull e00 = pkdup(wa1.x), e01 = pkdup(wa1.y), e10 = pkdup(wa1.z), e11 = pkdup(wa1.w);
            ull d20 = pkdup(kk.x),  d21 = pkdup(kk.y),  e20 = pkdup(kk.z),  e21 = pkdup(kk.w);
            #pragma unroll
            for (int m = 0; m < 13; ++m) {
                ulonglong2 qp = q[m * 16 + cp];
                if (m <= 10) {
                    Lo[m] = ffma2(qp.x, d00, Lo[m]); Lo[m] = ffma2(qp.y, e00, Lo[m]);
                    Hi[m] = ffma2(qp.x, d01, Hi[m]); Hi[m] = ffma2(qp.y, e01, Hi[m]);
                }
                if (m >= 1 && m <= 11) {
                    Lo[m-1] = ffma2(qp.x, d10, Lo[m-1]); Lo[m-1] = ffma2(qp.y, e10, Lo[m-1]);
                    Hi[m-1] = ffma2(qp.x, d11, Hi[m-1]); Hi[m-1] = ffma2(qp.y, e11, Hi[m-1]);
                }
                if (m >= 2) {
                    Lo[m-2] = ffma2(qp.x, d20, Lo[m-2]); Lo[m-2] = ffma2(qp.y, e20, Lo[m-2]);
                    Hi[m-2] = ffma2(qp.x, d21, Hi[m-2]); Hi[m-2] = ffma2(qp.y, e21, Hi[m-2]);
                }
            }
        }
    };

    // incremental: fresh conv2 positions {0,9,10}, both sets, reads via hoisted so7
    auto conv2_inc2 = [&](const ulonglong2* qs0, const ulonglong2* qs1,
                          ull (&nlo)[2][3], ull (&nhi)[2][3]) {
        #pragma unroll
        for (int s = 0; s < 2; ++s) {
            nlo[s][0] = nlo[s][1] = nlo[s][2] = b2lo;
            nhi[s][0] = nhi[s][1] = nhi[s][2] = b2hi;
        }
        #pragma unroll 4
        for (int cp = 0; cp < 16; ++cp) {
            float4 wa0 = w2xf[(2 * cp)     * 32 + lane];
            float4 wa1 = w2xf[(2 * cp + 1) * 32 + lane];
            float4 kk  = w2k2f4[cp * 32 + lane];
            ull d00 = pkdup(wa0.x), d01 = pkdup(wa0.y), d10 = pkdup(wa0.z), d11 = pkdup(wa0.w);
            ull e00 = pkdup(wa1.x), e01 = pkdup(wa1.y), e10 = pkdup(wa1.z), e11 = pkdup(wa1.w);
            ull d20 = pkdup(kk.x),  d21 = pkdup(kk.y),  e20 = pkdup(kk.z),  e21 = pkdup(kk.w);
            #pragma unroll
            for (int s = 0; s < 2; ++s) {
                const ulonglong2* q = s ? qs1 : qs0;
                ulonglong2 q0 = q[so7[0] + cp], q1 = q[so7[1] + cp], q2 = q[so7[2] + cp];
                nlo[s][0] = ffma2(q0.x, d00, nlo[s][0]); nlo[s][0] = ffma2(q0.y, e00, nlo[s][0]);
                nhi[s][0] = ffma2(q0.x, d01, nhi[s][0]); nhi[s][0] = ffma2(q0.y, e01, nhi[s][0]);
                nlo[s][0] = ffma2(q1.x, d10, nlo[s][0]); nlo[s][0] = ffma2(q1.y, e10, nlo[s][0]);
                nhi[s][0] = ffma2(q1.x, d11, nhi[s][0]); nhi[s][0] = ffma2(q1.y, e11, nhi[s][0]);
                nlo[s][0] = ffma2(q2.x, d20, nlo[s][0]); nlo[s][0] = ffma2(q2.y, e20, nlo[s][0]);
                nhi[s][0] = ffma2(q2.x, d21, nhi[s][0]); nhi[s][0] = ffma2(q2.y, e21, nhi[s][0]);

                ulonglong2 q9  = q[so7[3] + cp], q10 = q[so7[4] + cp];
                ulonglong2 q11 = q[so7[5] + cp], q12 = q[so7[6] + cp];
                nlo[s][1] = ffma2(q9.x,  d00, nlo[s][1]); nlo[s][1] = ffma2(q9.y,  e00, nlo[s][1]);
                nhi[s][1] = ffma2(q9.x,  d01, nhi[s][1]); nhi[s][1] = ffma2(q9.y,  e01, nhi[s][1]);
                nlo[s][1] = ffma2(q10.x, d10, nlo[s][1]); nlo[s][1] = ffma2(q10.y, e10, nlo[s][1]);
                nhi[s][1] = ffma2(q10.x, d11, nhi[s][1]); nhi[s][1] = ffma2(q10.y, e11, nhi[s][1]);
                nlo[s][1] = ffma2(q11.x, d20, nlo[s][1]); nlo[s][1] = ffma2(q11.y, e20, nlo[s][1]);
                nhi[s][1] = ffma2(q11.x, d21, nhi[s][1]); nhi[s][1] = ffma2(q11.y, e21, nhi[s][1]);

                nlo[s][2] = ffma2(q10.x, d00, nlo[s][2]); nlo[s][2] = ffma2(q10.y, e00, nlo[s][2]);
                nhi[s][2] = ffma2(q10.x, d01, nhi[s][2]); nhi[s][2] = ffma2(q10.y, e01, nhi[s][2]);
                nlo[s][2] = ffma2(q11.x, d10, nlo[s][2]); nlo[s][2] = ffma2(q11.y, e10, nlo[s][2]);
                nhi[s][2] = ffma2(q11.x, d11, nhi[s][2]); nhi[s][2] = ffma2(q11.y, e11, nhi[s][2]);
                nlo[s][2] = ffma2(q12.x, d20, nlo[s][2]); nlo[s][2] = ffma2(q12.y, e20, nlo[s][2]);
                nhi[s][2] = ffma2(q12.x, d21, nhi[s][2]); nhi[s][2] = ffma2(q12.y, e21, nhi[s][2]);
            }
        }
    };

    // merged tail: pool2 + dense2 + 4-way parity reduce + dense1 + recurrence +
    // new-column ring write (replaces the register-window shfl shift)
    auto tail4 = [&](auto&& gLo0, auto&& gHi0, auto&& gLo1, auto&& gHi1, int t, int bX) {
        ull sA0[5] = {0,0,0,0,0}, sB0[5] = {0,0,0,0,0};
        ull sA1[5] = {0,0,0,0,0}, sB1[5] = {0,0,0,0,0};
        #pragma unroll
        for (int jj = 0; jj < 6; ++jj) {
            ull fapA0, fbpA0, fapB0, fbpB0, fapA1, fbpA1, fapB1, fbpB1;
            float aA, aB, bA, bB;
            if (jj < 5) {
                unpk(gLo0(2 * jj), aA, aB); unpk(gLo0(2 * jj + 1), bA, bB);
                fapA0 = pkdup(fmaxf(fmaxf(aA, 0.f), fmaxf(bA, 0.f)));
                fapB0 = pkdup(fmaxf(fmaxf(aB, 0.f), fmaxf(bB, 0.f)));
                unpk(gHi0(2 * jj), aA, aB); unpk(gHi0(2 * jj + 1), bA, bB);
                fbpA0 = pkdup(fmaxf(fmaxf(aA, 0.f), fmaxf(bA, 0.f)));
                fbpB0 = pkdup(fmaxf(fmaxf(aB, 0.f), fmaxf(bB, 0.f)));
                unpk(gLo1(2 * jj), aA, aB); unpk(gLo1(2 * jj + 1), bA, bB);
                fapA1 = pkdup(fmaxf(fmaxf(aA, 0.f), fmaxf(bA, 0.f)));
                fapB1 = pkdup(fmaxf(fmaxf(aB, 0.f), fmaxf(bB, 0.f)));
                unpk(gHi1(2 * jj), aA, aB); unpk(gHi1(2 * jj + 1), bA, bB);
                fbpA1 = pkdup(fmaxf(fmaxf(aA, 0.f), fmaxf(bA, 0.f)));
                fbpB1 = pkdup(fmaxf(fmaxf(aB, 0.f), fmaxf(bB, 0.f)));
            } else {
                unpk(gLo0(10), aA, aB);
                fapA0 = pkdup(fmaxf(aA, 0.f)); fapB0 = pkdup(fmaxf(aB, 0.f));
                unpk(gHi0(10), aA, aB);
                fbpA0 = pkdup(fmaxf(aA, 0.f)); fbpB0 = pkdup(fmaxf(aB, 0.f));
                unpk(gLo1(10), aA, aB);
                fapA1 = pkdup(fmaxf(aA, 0.f)); fapB1 = pkdup(fmaxf(aB, 0.f));
                unpk(gHi1(10), aA, aB);
                fbpA1 = pkdup(fmaxf(aA, 0.f)); fbpB1 = pkdup(fmaxf(aB, 0.f));
            }
            #pragma unroll
            for (int q = 0; q < 5; ++q) {
                ulonglong2 w = wdx[(q * 6 + jj) * 32 + lane];   // one load, 4 vehicles
                sA0[q] = ffma2(fapA0, w.x, sA0[q]); sA0[q] = ffma2(fbpA0, w.y, sA0[q]);
                sB0[q] = ffma2(fapB0, w.x, sB0[q]); sB0[q] = ffma2(fbpB0, w.y, sB0[q]);
                sA1[q] = ffma2(fapA1, w.x, sA1[q]); sA1[q] = ffma2(fbpA1, w.y, sA1[q]);
                sB1[q] = ffma2(fapB1, w.x, sB1[q]); sB1[q] = ffma2(fbpB1, w.y, sB1[q]);
            }
        }
        const bool bit0 = (lane & 1), bit1 = (lane & 2);
        ull r0[5], r1[5], s5[5];
        #pragma unroll
        for (int q = 0; q < 5; ++q) {
            ull z = bit0 ? sB0[q] : sA0[q];
            ull x = bit0 ? sA0[q] : sB0[q];
            r0[q] = addf32x2(z, __shfl_xor_sync(0xffffffffu, x, 1));
            z = bit0 ? sB1[q] : sA1[q];
            x = bit0 ? sA1[q] : sB1[q];
            r1[q] = addf32x2(z, __shfl_xor_sync(0xffffffffu, x, 1));
        }
        #pragma unroll
        for (int q = 0; q < 5; ++q) {
            ull z = bit1 ? r1[q] : r0[q];
            ull x = bit1 ? r0[q] : r1[q];
            s5[q] = addf32x2(z, __shfl_xor_sync(0xffffffffu, x, 2));
        }
        #pragma unroll
        for (int off = 4; off <= 16; off <<= 1) {
            #pragma unroll
            for (int q = 0; q < 5; ++q)
                s5[q] = addf32x2(s5[q], __shfl_xor_sync(0xffffffffu, s5[q], off));
        }
        float d[10];
        #pragma unroll
        for (int q = 0; q < 5; ++q) unpk(s5[q], d[2 * q], d[2 * q + 1]);
        float y = sm[BD1_OFF];
        #pragma unroll
        for (int o = 0; o < 10; ++o)
            y = fmaf(fmaxf(d[o] + sm[BD2_OFF + o], 0.0f), sm[WD1_OFF + o], y);
        float accv = fmaf(10.0f, y, -6.0f);
        float av[4];
        #pragma unroll
        for (int i = 0; i < 4; ++i) av[i] = __shfl_sync(0xffffffffu, accv, i);

        float pp[4], ps[4];
        #pragma unroll
        for (int i = 0; i < 4; ++i) {
            pp[i] = fmaf(0.1f, s24v[i], p24v[i]);
            ps[i] = fmaf(0.1f, av[i],   s24v[i]);
            p24v[i] = pp[i]; s24v[i] = ps[i];
        }
        if (lane < 4) out2base[lane * NT + t] = make_float2(pp[lane], ps[lane]);

        // new column for step t+1 at ring slot (bX + 25) & 31
        if (t < NT - 1) {
            int ws = ((bX + 25) & 31) * 8;
            if (lane == 0) {
                *(float4*)(xr0 + ws) = make_float4(
                    (ldnv[0].x - pp[0]) * (1.0f / 200.0f),
                    (ldnv[1].x - pp[1]) * (1.0f / 200.0f),
                    ps[0] * (1.0f / 40.0f),
                    ps[1] * (1.0f / 40.0f));
                *(float2*)(xr0 + ws + 4) = make_float2(
                    ldnv[0].y * (1.0f / 40.0f),
                    ldnv[1].y * (1.0f / 40.0f));
            } else if (lane == 1) {
                *(float4*)(xr1 + ws) = make_float4(
                    (ldnv[2].x - pp[2]) * (1.0f / 200.0f),
                    (ldnv[3].x - pp[3]) * (1.0f / 200.0f),
                    ps[2] * (1.0f / 40.0f),
                    ps[3] * (1.0f / 40.0f));
                *(float2*)(xr1 + ws + 4) = make_float2(
                    ldnv[2].y * (1.0f / 40.0f),
                    ldnv[3].y * (1.0f / 40.0f));
            }
        }
    };

    // ---------- seed steps (full compute) ----------
    ull Rlo0[11], Rhi0[11], Rlo1[11], Rhi1[11];   // even-parity conv2 state (registers)
    #pragma unroll
    for (int i = 0; i < 4; ++i) ldnv[i] = lead2base[i * LEADLEN + 0 + PAST];
    conv1_full_ring(xr0, pqE0, 0); conv1_full_ring(xr1, pqE1, 0);
    __syncwarp();
    conv2_full(qE0, Rlo0, Rhi0);
    conv2_full(qE1, Rlo1, Rhi1);
    tail4([&](int j){ return Rlo0[j]; }, [&](int j){ return Rhi0[j]; },
          [&](int j){ return Rlo1[j]; }, [&](int j){ return Rhi1[j]; }, 0, 0);

    {
        #pragma unroll
        for (int i = 0; i < 4; ++i) ldnv[i] = lead2base[i * LEADLEN + 1 + PAST];
        __syncwarp();   // ring write from step 0 visible to conv1 reads
        conv1_full_ring(xr0, pqO0, 1); conv1_full_ring(xr1, pqO1, 1);
        __syncwarp();
        ull Tlo0[11], Thi0[11], Tlo1[11], Thi1[11];
        conv2_full(qO0, Tlo0, Thi0);
        conv2_full(qO1, Tlo1, Thi1);
        tail4([&](int j){ return Tlo0[j]; }, [&](int j){ return Thi0[j]; },
              [&](int j){ return Tlo1[j]; }, [&](int j){ return Thi1[j]; }, 1, 1);
        #pragma unroll
        for (int j = 0; j < 11; ++j) {
            ScLo0[j * 32 + lane] = Tlo0[j]; ScHi0[j * 32 + lane] = Thi0[j];
            ScLo1[j * 32 + lane] = Tlo1[j]; ScHi1[j * 32 + lane] = Thi1[j];
        }
    }

    // ---------- main incremental loop ----------
    #pragma unroll 1
    for (int t = 2; t < NT; t += 2) {
        // ===== even step t : register conv2 state, pool1-even circular =====
        #pragma unroll
        for (int i = 0; i < 4; ++i) ldnv[i] = lead2base[i * LEADLEN + t + PAST];
        __syncwarp();   // prev ring/state writes visible
        bPe = wrap13(bPe + 1);
        int bXe = t & 31;
        {
            int w0i = bPe, w11i = wrap13(bPe + 11), w12i = wrap13(bPe + 12);
            conv1_fresh_ring(xr0, pqE0, bXe, w0i, w11i, w12i);
            conv1_fresh_ring(xr1, pqE1, bXe, w0i, w11i, w12i);
            __syncwarp();
            so7[0] = bPe * 16;
            so7[1] = wrap13(bPe + 1) * 16;
            so7[2] = wrap13(bPe + 2) * 16;
            so7[3] = wrap13(bPe + 9) * 16;
            so7[4] = wrap13(bPe + 10) * 16;
            so7[5] = w11i * 16;
            so7[6] = w12i * 16;
        }
        {
            ull nlo[2][3], nhi[2][3];
            conv2_inc2(qE0, qE1, nlo, nhi);
            Rlo0[0] = nlo[0][0]; Rhi0[0] = nhi[0][0];
            Rlo1[0] = nlo[1][0]; Rhi1[0] = nhi[1][0];
            #pragma unroll
            for (int j = 1; j <= 8; ++j) {
                Rlo0[j] = Rlo0[j + 1]; Rhi0[j] = Rhi0[j + 1];
                Rlo1[j] = Rlo1[j + 1]; Rhi1[j] = Rhi1[j + 1];
            }
            Rlo0[9] = nlo[0][1]; Rlo0[10] = nlo[0][2];
            Rhi0[9] = nhi[0][1]; Rhi0[10] = nhi[0][2];
            Rlo1[9] = nlo[1][1]; Rlo1[10] = nlo[1][2];
            Rhi1[9] = nhi[1][1]; Rhi1[10] = nhi[1][2];
        }
        tail4([&](int j){ return Rlo0[j]; }, [&](int j){ return Rhi0[j]; },
              [&](int j){ return Rlo1[j]; }, [&](int j){ return Rhi1[j]; }, t, bXe);

        // ===== odd step t+1 : circular smem conv2 state, pool1-odd circular =====
        if ((t + 1) < NT - 1) {
            #pragma unroll
            for (int i = 0; i < 4; ++i) ldnv[i] = lead2base[i * LEADLEN + t + 1 + PAST];
        }
        __syncwarp();
        bPo = wrap13(bPo + 1);
        int bXo = (t + 1) & 31;
        {
            int w0i = bPo, w11i = wrap13(bPo + 11), w12i = wrap13(bPo + 12);
            conv1_fresh_ring(xr0, pqO0, bXo, w0i, w11i, w12i);
            conv1_fresh_ring(xr1, pqO1, bXo, w0i, w11i, w12i);
            __syncwarp();
            so7[0] = bPo * 16;
            so7[1] = wrap13(bPo + 1) * 16;
            so7[2] = wrap13(bPo + 2) * 16;
            so7[3] = wrap13(bPo + 9) * 16;
            so7[4] = wrap13(bPo + 10) * 16;
            so7[5] = w11i * 16;
            so7[6] = w12i * 16;
        }
        {
            ull mlo[2][3], mhi[2][3];
            conv2_inc2(qO0, qO1, mlo, mhi);
            bS = wrap11(bS + 1);
            // fresh positions {0,9,10} forwarded from registers; 1..8 from smem
            tail4(
              [&](int j){ return j == 0 ? mlo[0][0] : (j == 9 ? mlo[0][1] : (j == 10 ? mlo[0][2]
                               : ScLo0[wrap11(bS + j) * 32 + lane])); },
              [&](int j){ return j == 0 ? mhi[0][0] : (j == 9 ? mhi[0][1] : (j == 10 ? mhi[0][2]
                               : ScHi0[wrap11(bS + j) * 32 + lane])); },
              [&](int j){ return j == 0 ? mlo[1][0] : (j == 9 ? mlo[1][1] : (j == 10 ? mlo[1][2]
                               : ScLo1[wrap11(bS + j) * 32 + lane])); },
              [&](int j){ return j == 0 ? mhi[1][0] : (j == 9 ? mhi[1][1] : (j == 10 ? mhi[1][2]
                               : ScHi1[wrap11(bS + j) * 32 + lane])); },
              t + 1, bXo);
            // deferred state writes (first needed at step t+3; slots disjoint from reads)
            int i0 = bS * 32 + lane;
            int i9 = wrap11(bS + 9) * 32 + lane;
            int iX = wrap11(bS + 10) * 32 + lane;
            ScLo0[i0] = mlo[0][0]; ScLo0[i9] = mlo[0][1]; ScLo0[iX] = mlo[0][2];
            ScHi0[i0] = mhi[0][0]; ScHi0[i9] = mhi[0][1]; ScHi0[iX] = mhi[0][2];
            ScLo1[i0] = mlo[1][0]; ScLo1[i9] = mlo[1][1]; ScLo1[iX] = mlo[1][2];
            ScHi1[i0] = mhi[1][0]; ScHi1[i9] = mhi[1][1]; ScHi1[iX] = mhi[1][2];
        }
    }
}

extern "C" void kernel_launch(void* const* d_in, const int* in_sizes, int n_in,
                              void* d_out, int out_size)
{
    const float* lead = (const float*)d_in[0];   // (4096, 280, 2)
    const float* cur  = (const float*)d_in[1];   // (4096, 25, 2)
    // d_in[2] = mask (unused by the reference computation)
    const float* w1  = (const float*)d_in[3];
    const float* b1  = (const float*)d_in[4];
    const float* w2  = (const float*)d_in[5];
    const float* b2  = (const float*)d_in[6];
    const float* wd2 = (const float*)d_in[7];
    const float* bd2 = (const float*)d_in[8];
    const float* wd1 = (const float*)d_in[9];
    const float* bd1 = (const float*)d_in[10];
    float* out = (float*)d_out;                   // (4096, 256, 2)

    (void)in_sizes; (void)n_in; (void)out_size;

    size_t smem_bytes = (size_t)SMEM_FLOATS * sizeof(float);   // 227936 B
    cudaFuncSetAttribute(rnncf_kernel,
                         cudaFuncAttributeMaxDynamicSharedMemorySize,
                         (int)smem_bytes);
    rnncf_kernel<<<NCTA, NTHREADS, smem_bytes>>>(
        lead, cur, w1, b1, w2, b2, wd2, bd2, wd1, bd1, out);
}